// round 1
// baseline (speedup 1.0000x reference)
#include <cuda_runtime.h>
#include <cuda_bf16.h>
#include <cstdint>

#define NTOT 65536
#define DDIM 512
#define KCL  64

#define BN 128
#define BK 32
#define DTILES (DDIM / BN)          // 4
#define NCHUNKS 128
#define RPC (NTOT / NCHUNKS)        // 512 rows per chunk
#define ITERS (RPC / BK)            // 16
#define SK 34                       // padded smem stride (elements, even for 4B alignment)

__device__ float  g_partial[KCL * DDIM];
__device__ float  g_h2sum;
__device__ double g_proj;

__global__ void k_zero() {
    int i = blockIdx.x * 256 + threadIdx.x;
    if (i < KCL * DDIM) g_partial[i] = 0.f;
    if (i == 0) { g_h2sum = 0.f; g_proj = 0.0; }
}

__device__ __forceinline__ uint32_t pack_bf16(float a, float b) {
    __nv_bfloat162 p;
    p.x = __float2bfloat16_rn(a);
    p.y = __float2bfloat16_rn(b);
    return *reinterpret_cast<uint32_t*>(&p);
}

__global__ __launch_bounds__(256, 2)
void k_gemm(const float* __restrict__ H, const float* __restrict__ Fm) {
    // Fs: A-operand tile, stored [m][kk] (m = cluster index 0..63, kk = contraction)
    // Hs: B-operand tile, stored [n][kk] (n = d-column within tile)
    __shared__ __align__(16) __nv_bfloat16 Fs[2][KCL * SK];
    __shared__ __align__(16) __nv_bfloat16 Hs[2][BN * SK];
    __shared__ float redbuf[8];

    const int tid  = threadIdx.x;
    const int lane = tid & 31;
    const int wid  = tid >> 5;
    const int d0   = blockIdx.x * BN;
    const int nb0  = blockIdx.y * RPC;

    const int wm = (wid >> 2) * 32;     // warp m-offset (2 warps along m)
    const int wn = (wid & 3) * 32;      // warp n-offset (4 warps along n)
    const int g  = lane >> 2;
    const int t  = lane & 3;

    // global-load task mapping
    const int f_kk  = (tid >> 4) << 1;  // 0,2,..,30
    const int f_m   = (tid & 15) << 2;  // 0,4,..,60
    const int h_kk0 = (tid >> 5) << 1;  // 0..14 even
    const int h_kk1 = h_kk0 + 16;       // 16..30 even
    const int h_n0  = lane << 2;        // 0..124

    float acc[2][4][4];
#pragma unroll
    for (int a = 0; a < 2; a++)
#pragma unroll
        for (int b = 0; b < 4; b++)
#pragma unroll
            for (int c = 0; c < 4; c++) acc[a][b][c] = 0.f;

    float h2 = 0.f;

    float4 fa, fb, ha0, ha1, hb0, hb1;

    auto gload = [&](int nb) {
        fa  = *(const float4*)&Fm[(size_t)(nb + f_kk)      * KCL  + f_m];
        fb  = *(const float4*)&Fm[(size_t)(nb + f_kk + 1)  * KCL  + f_m];
        ha0 = *(const float4*)&H [(size_t)(nb + h_kk0)     * DDIM + d0 + h_n0];
        ha1 = *(const float4*)&H [(size_t)(nb + h_kk0 + 1) * DDIM + d0 + h_n0];
        hb0 = *(const float4*)&H [(size_t)(nb + h_kk1)     * DDIM + d0 + h_n0];
        hb1 = *(const float4*)&H [(size_t)(nb + h_kk1 + 1) * DDIM + d0 + h_n0];
    };

    auto sstore = [&](int buf) {
        __nv_bfloat16* fs = Fs[buf];
        __nv_bfloat16* hs = Hs[buf];
        const float* pa = &fa.x;  const float* pb = &fb.x;
#pragma unroll
        for (int j = 0; j < 4; j++)
            *(uint32_t*)&fs[(f_m + j) * SK + f_kk] = pack_bf16(pa[j], pb[j]);
        const float* q0 = &ha0.x; const float* q1 = &ha1.x;
        const float* r0 = &hb0.x; const float* r1 = &hb1.x;
#pragma unroll
        for (int j = 0; j < 4; j++) {
            *(uint32_t*)&hs[(h_n0 + j) * SK + h_kk0] = pack_bf16(q0[j], q1[j]);
            *(uint32_t*)&hs[(h_n0 + j) * SK + h_kk1] = pack_bf16(r0[j], r1[j]);
            h2 += q0[j]*q0[j] + q1[j]*q1[j] + r0[j]*r0[j] + r1[j]*r1[j];
        }
    };

    auto compute = [&](int buf) {
        const __nv_bfloat16* fs = Fs[buf];
        const __nv_bfloat16* hs = Hs[buf];
#pragma unroll
        for (int ks = 0; ks < BK; ks += 16) {
            uint32_t a[2][4], b[4][2];
#pragma unroll
            for (int mi = 0; mi < 2; mi++) {
                const __nv_bfloat16* p = &fs[(wm + mi * 16 + g) * SK + ks + 2 * t];
                a[mi][0] = *(const uint32_t*)(p);
                a[mi][1] = *(const uint32_t*)(p + 8 * SK);
                a[mi][2] = *(const uint32_t*)(p + 8);
                a[mi][3] = *(const uint32_t*)(p + 8 * SK + 8);
            }
#pragma unroll
            for (int ni = 0; ni < 4; ni++) {
                const __nv_bfloat16* p = &hs[(wn + ni * 8 + g) * SK + ks + 2 * t];
                b[ni][0] = *(const uint32_t*)(p);
                b[ni][1] = *(const uint32_t*)(p + 8);
            }
#pragma unroll
            for (int mi = 0; mi < 2; mi++)
#pragma unroll
                for (int ni = 0; ni < 4; ni++) {
                    asm volatile(
                        "mma.sync.aligned.m16n8k16.row.col.f32.bf16.bf16.f32 "
                        "{%0,%1,%2,%3}, {%4,%5,%6,%7}, {%8,%9}, {%0,%1,%2,%3};\n"
                        : "+f"(acc[mi][ni][0]), "+f"(acc[mi][ni][1]),
                          "+f"(acc[mi][ni][2]), "+f"(acc[mi][ni][3])
                        : "r"(a[mi][0]), "r"(a[mi][1]), "r"(a[mi][2]), "r"(a[mi][3]),
                          "r"(b[ni][0]), "r"(b[ni][1]));
                }
        }
    };

    gload(nb0);
    sstore(0);
    __syncthreads();

#pragma unroll 1
    for (int it = 0; it < ITERS; ++it) {
        int buf = it & 1;
        if (it + 1 < ITERS) gload(nb0 + (it + 1) * BK);
        compute(buf);
        if (it + 1 < ITERS) sstore(buf ^ 1);
        __syncthreads();
    }

    // accumulate partial G into global buffer
#pragma unroll
    for (int mi = 0; mi < 2; mi++)
#pragma unroll
        for (int ni = 0; ni < 4; ni++) {
            int row = wm + mi * 16 + g;
            int col = d0 + wn + ni * 8 + 2 * t;
            atomicAdd(&g_partial[row * DDIM + col],           acc[mi][ni][0]);
            atomicAdd(&g_partial[row * DDIM + col + 1],       acc[mi][ni][1]);
            atomicAdd(&g_partial[(row + 8) * DDIM + col],     acc[mi][ni][2]);
            atomicAdd(&g_partial[(row + 8) * DDIM + col + 1], acc[mi][ni][3]);
        }

    // block-reduce h^2, one atomic per CTA
#pragma unroll
    for (int o = 16; o > 0; o >>= 1) h2 += __shfl_xor_sync(0xffffffffu, h2, o);
    if (lane == 0) redbuf[wid] = h2;
    __syncthreads();
    if (tid == 0) {
        float s = 0.f;
#pragma unroll
        for (int w = 0; w < 8; w++) s += redbuf[w];
        atomicAdd(&g_h2sum, s);
    }
}

__global__ void k_proj() {
    int idx = blockIdx.x * 256 + threadIdx.x;
    double s = 0.0;
    for (int i = idx; i < KCL * DDIM; i += 32 * 256) {
        double v = (double)g_partial[i];
        s += v * v;
    }
#pragma unroll
    for (int o = 16; o > 0; o >>= 1) s += __shfl_xor_sync(0xffffffffu, s, o);
    __shared__ double sb[8];
    if ((threadIdx.x & 31) == 0) sb[threadIdx.x >> 5] = s;
    __syncthreads();
    if (threadIdx.x == 0) {
        double tot = 0.0;
#pragma unroll
        for (int w = 0; w < 8; w++) tot += sb[w];
        atomicAdd(&g_proj, tot);
    }
}

__global__ void k_final(float* out) {
    out[0] = (float)((double)g_h2sum - g_proj);
}

extern "C" void kernel_launch(void* const* d_in, const int* in_sizes, int n_in,
                              void* d_out, int out_size) {
    const float* Hp;
    const float* Fp;
    if (in_sizes[0] == NTOT * DDIM) {
        Hp = (const float*)d_in[0];
        Fp = (const float*)d_in[1];
    } else {
        Hp = (const float*)d_in[1];
        Fp = (const float*)d_in[0];
    }

    k_zero<<<(KCL * DDIM + 255) / 256, 256>>>();
    dim3 grid(DTILES, NCHUNKS);
    k_gemm<<<grid, 256>>>(Hp, Fp);
    k_proj<<<32, 256>>>();
    k_final<<<1, 1>>>((float*)d_out);
}